// round 1
// baseline (speedup 1.0000x reference)
#include <cuda_runtime.h>
#include <math.h>

#define BATCH 16
#define SEQ   512
#define NDIM  32
#define NMAT  (BATCH*SEQ)     // 8192
#define FDIM  (NDIM*NDIM)     // 1024

// ---------------- scratch (static __device__, allocation-free) ----------------
__device__ float d_xl[NMAT*FDIM];          // logm result, diag zeroed
__device__ float d_q [NMAT*FDIM];
__device__ float d_k [NMAT*FDIM];
__device__ float d_v [NMAT*FDIM];
__device__ float d_sc[BATCH*SEQ*SEQ];      // scores -> exp(scores)
__device__ float d_isum[BATCH*SEQ];        // 1/colsum of exp
__device__ float d_C [3*FDIM];             // cayley matrices for q,k,v
__device__ float d_q2[NMAT];
__device__ float d_k2[NMAT];

// ---------------- Cayley: C = (I - X) (I + X)^-1, X = W - W^T -----------------
// Solve (I - X) Z = (I + X); C = Z^T. One warp, Gauss-Jordan, no pivoting
// (symmetric part of I-X is I => pivots >= 1, stable).
__global__ void cayley_kernel(const float* __restrict__ qw,
                              const float* __restrict__ kw,
                              const float* __restrict__ vw) {
    __shared__ float Aug[32][65];
    const int lane = threadIdx.x;
    for (int w = 0; w < 3; w++) {
        const float* W = (w == 0) ? qw : (w == 1) ? kw : vw;
        for (int r = 0; r < 32; r++) {
            float xv = W[r*32 + lane] - W[lane*32 + r];
            float id = (r == lane) ? 1.f : 0.f;
            Aug[r][lane]      = id - xv;   // A = I - X
            Aug[r][32 + lane] = id + xv;   // B = I + X
        }
        __syncwarp();
        for (int kp = 0; kp < 32; kp++) {
            float ip = 1.f / Aug[kp][kp];
            __syncwarp();
            Aug[kp][lane]      *= ip;
            Aug[kp][32 + lane] *= ip;
            __syncwarp();
            for (int r = 0; r < 32; r++) {
                if (r == kp) continue;
                float f = Aug[r][kp];
                Aug[r][lane]      = fmaf(-f, Aug[kp][lane],      Aug[r][lane]);
                Aug[r][32 + lane] = fmaf(-f, Aug[kp][32 + lane], Aug[r][32 + lane]);
            }
            __syncwarp();
        }
        // C[i][j] = Z[j][i] = Aug[j][32+i]
        for (int i = 0; i < 32; i++)
            d_C[w*FDIM + i*32 + lane] = Aug[lane][32 + i];
        __syncwarp();
    }
}

// ---------------- one-sided Jacobi logm: one warp per 32x32 SPD matrix --------
// Thread t owns column t in registers. After convergence g_t = lambda_t v_t,
// so logm = sum_t (log l / l^2) g_t g_t^T. Output with zeroed diagonal.
__global__ void __launch_bounds__(256) jacobi_logm_kernel(const float* __restrict__ x) {
    const int lane = threadIdx.x & 31;
    const int wip  = threadIdx.x >> 5;
    const int m    = blockIdx.x * 8 + wip;
    const unsigned FULL = 0xffffffffu;
    const float* A = x + (size_t)m * FDIM;

    float g[32];
#pragma unroll
    for (int r = 0; r < 32; r++) g[r] = A[r*32 + lane];
    float nrm = 0.f;
#pragma unroll
    for (int r = 0; r < 32; r++) nrm = fmaf(g[r], g[r], nrm);

    for (int sweep = 0; sweep < 12; sweep++) {
        bool any_rot = false;
        for (int rr = 0; rr < 31; rr++) {
            // round-robin pairing: lane31 <-> rr; else (2rr - i) mod 31 (self -> 31)
            int partner;
            if (lane == 31) partner = rr;
            else {
                int p = (2*rr - lane + 62) % 31;
                partner = (p == lane) ? 31 : p;
            }
            float h[32];
#pragma unroll
            for (int r2 = 0; r2 < 32; r2++) h[r2] = __shfl_sync(FULL, g[r2], partner);
            float apq = 0.f;
#pragma unroll
            for (int r2 = 0; r2 < 32; r2++) apq = fmaf(g[r2], h[r2], apq);
            float other = __shfl_sync(FULL, nrm, partner);
            const bool is_p = lane < partner;
            float app = is_p ? nrm : other;
            float aqq = is_p ? other : nrm;
            float c = 1.f, s = 0.f;
            if (apq * apq > 1e-14f * app * aqq) {
                any_rot = true;
                float tau = (aqq - app) / (2.f * apq);
                float t   = copysignf(1.f, tau) / (fabsf(tau) + sqrtf(fmaf(tau, tau, 1.f)));
                c = rsqrtf(fmaf(t, t, 1.f));
                s = t * c;
            }
            float sp = is_p ? -s : s;
#pragma unroll
            for (int r2 = 0; r2 < 32; r2++) g[r2] = fmaf(sp, h[r2], c * g[r2]);
            nrm = c*c*nrm + s*s*other + 2.f*c*sp*apq;
        }
        if (!__any_sync(FULL, any_rot)) break;
    }

    // exact norm, alpha = log(lambda)/lambda^2 = 0.5*log(nrm)/nrm
    nrm = 0.f;
#pragma unroll
    for (int r = 0; r < 32; r++) nrm = fmaf(g[r], g[r], nrm);
    float alpha = 0.5f * logf(nrm) / nrm;

    __shared__ float Gs[8][32][33];
    __shared__ float Al[8][32];
#pragma unroll
    for (int r = 0; r < 32; r++) Gs[wip][r][lane] = g[r];
    Al[wip][lane] = alpha;
    __syncwarp();

    float acc[32];
#pragma unroll
    for (int r = 0; r < 32; r++) acc[r] = 0.f;
#pragma unroll 4
    for (int t = 0; t < 32; t++) {
        float coef = Al[wip][t] * Gs[wip][lane][t];   // alpha_t * g_t[lane]
#pragma unroll
        for (int r = 0; r < 32; r++)
            acc[r] = fmaf(coef, Gs[wip][r][t], acc[r]);  // broadcast read
    }
    float* out = d_xl + (size_t)m * FDIM;
#pragma unroll
    for (int r = 0; r < 32; r++)
        out[r*32 + lane] = (r == lane) ? 0.f : acc[r];
}

// ---------------- transform: y_w = zero_diag(C_w xl C_w^T), + q2/k2 ----------
__global__ void transform_kernel() {
    const int m = blockIdx.x;
    const int j = threadIdx.x, i = threadIdx.y;
    __shared__ float Xs[32][33], Ts[32][33], Cs[32][33], red[32];
    Xs[i][j] = d_xl[(size_t)m*FDIM + i*32 + j];
    for (int w = 0; w < 3; w++) {
        __syncthreads();
        Cs[i][j] = d_C[w*FDIM + i*32 + j];
        __syncthreads();
        float t = 0.f;
#pragma unroll
        for (int kk = 0; kk < 32; kk++) t = fmaf(Cs[i][kk], Xs[kk][j], t);
        Ts[i][j] = t;
        __syncthreads();
        float y = 0.f;
#pragma unroll
        for (int kk = 0; kk < 32; kk++) y = fmaf(Ts[i][kk], Cs[j][kk], y);
        if (i == j) y = 0.f;
        float* o = (w == 0) ? d_q : (w == 1) ? d_k : d_v;
        o[(size_t)m*FDIM + i*32 + j] = y;
        if (w < 2) {
            float sq = y * y;
#pragma unroll
            for (int off = 16; off; off >>= 1) sq += __shfl_down_sync(0xffffffffu, sq, off);
            if (j == 0) red[i] = sq;
            __syncthreads();
            if (i == 0) {
                float v2 = red[j];
#pragma unroll
                for (int off = 16; off; off >>= 1) v2 += __shfl_down_sync(0xffffffffu, v2, off);
                if (j == 0) { if (w == 0) d_q2[m] = v2; else d_k2[m] = v2; }
            }
        }
    }
}

// ---------------- scores GEMM: S[j][i] = kf[j].qf[i]; -> scores --------------
__global__ void __launch_bounds__(256) scores_kernel() {
    const int b  = blockIdx.z;
    const int mt = blockIdx.y * 64;   // j rows
    const int nt = blockIdx.x * 64;   // i cols
    const float* Ab = d_k + (size_t)b * SEQ * FDIM;
    const float* Bb = d_q + (size_t)b * SEQ * FDIM;
    __shared__ __align__(16) float As[16][68];
    __shared__ __align__(16) float Bs[16][68];
    const int tid = threadIdx.x;
    const int lr = tid >> 2, lc = (tid & 3) << 2;
    const int tx = tid & 15, ty = tid >> 4;
    float acc[4][4];
#pragma unroll
    for (int ii = 0; ii < 4; ii++)
#pragma unroll
        for (int jj = 0; jj < 4; jj++) acc[ii][jj] = 0.f;

    for (int kt = 0; kt < FDIM; kt += 16) {
        float4 av = *(const float4*)(Ab + (size_t)(mt + lr)*FDIM + kt + lc);
        float4 bv = *(const float4*)(Bb + (size_t)(nt + lr)*FDIM + kt + lc);
        __syncthreads();
        As[lc+0][lr]=av.x; As[lc+1][lr]=av.y; As[lc+2][lr]=av.z; As[lc+3][lr]=av.w;
        Bs[lc+0][lr]=bv.x; Bs[lc+1][lr]=bv.y; Bs[lc+2][lr]=bv.z; Bs[lc+3][lr]=bv.w;
        __syncthreads();
#pragma unroll
        for (int kk = 0; kk < 16; kk++) {
            const float4 a  = *(const float4*)(&As[kk][ty << 2]);
            const float4 bq = *(const float4*)(&Bs[kk][tx << 2]);
            float ar[4] = {a.x, a.y, a.z, a.w};
            float br[4] = {bq.x, bq.y, bq.z, bq.w};
#pragma unroll
            for (int ii = 0; ii < 4; ii++)
#pragma unroll
                for (int jj = 0; jj < 4; jj++)
                    acc[ii][jj] = fmaf(ar[ii], br[jj], acc[ii][jj]);
        }
    }
    const int jrow = mt + (ty << 2);
    const int icol = nt + (tx << 2);
    float k2r[4], q2c[4];
#pragma unroll
    for (int ii = 0; ii < 4; ii++) k2r[ii] = d_k2[b*SEQ + jrow + ii];
#pragma unroll
    for (int jj = 0; jj < 4; jj++) q2c[jj] = d_q2[b*SEQ + icol + jj];
#pragma unroll
    for (int ii = 0; ii < 4; ii++)
#pragma unroll
        for (int jj = 0; jj < 4; jj++) {
            float dist2 = fmaxf(k2r[ii] + q2c[jj] - 2.f*acc[ii][jj], 1e-12f);
            float e  = sqrtf(dist2);
            float sc = 1.f / (1.f + log1pf(e));
            d_sc[((size_t)b*SEQ + jrow + ii)*SEQ + icol + jj] = sc;
        }
}

// ---------------- softmax over j (rows): exp in place + 1/colsum ------------
__global__ void softmax_kernel() {
    const int b = blockIdx.y;
    const int i = blockIdx.x * 128 + threadIdx.x;
    float* S = d_sc + (size_t)b * SEQ * SEQ;
    float sum = 0.f;
    for (int j = 0; j < SEQ; j++) {
        float e = expf(S[(size_t)j*SEQ + i]);
        S[(size_t)j*SEQ + i] = e;
        sum += e;
    }
    d_isum[b*SEQ + i] = 1.f / sum;
}

// ---------------- out GEMM: out[b,c,f] = sum_a e[c,a]*isum[a]*v[a,f] --------
__global__ void __launch_bounds__(256) out_kernel(float* __restrict__ out) {
    const int b  = blockIdx.z;
    const int mt = blockIdx.y * 64;   // c
    const int nt = blockIdx.x * 64;   // f
    const float* Ab = d_sc + (size_t)b * SEQ * SEQ;
    const float* Bb = d_v  + (size_t)b * SEQ * FDIM;
    const float* isum = d_isum + b * SEQ;
    __shared__ __align__(16) float As[16][68];
    __shared__ __align__(16) float Bs[16][68];
    const int tid = threadIdx.x;
    const int alr = tid >> 2,  alc = (tid & 3)  << 2;   // A: 64 rows x 16 k
    const int blr = tid >> 4,  blc = (tid & 15) << 2;   // B: 16 k-rows x 64 n
    const int tx = tid & 15, ty = tid >> 4;
    float acc[4][4];
#pragma unroll
    for (int ii = 0; ii < 4; ii++)
#pragma unroll
        for (int jj = 0; jj < 4; jj++) acc[ii][jj] = 0.f;

    for (int kt = 0; kt < SEQ; kt += 16) {
        float4 av = *(const float4*)(Ab + (size_t)(mt + alr)*SEQ  + kt + alc);
        float4 bv = *(const float4*)(Bb + (size_t)(kt + blr)*FDIM + nt + blc);
        float sc = isum[kt + blr];
        __syncthreads();
        As[alc+0][alr]=av.x; As[alc+1][alr]=av.y; As[alc+2][alr]=av.z; As[alc+3][alr]=av.w;
        *(float4*)(&Bs[blr][blc]) = make_float4(bv.x*sc, bv.y*sc, bv.z*sc, bv.w*sc);
        __syncthreads();
#pragma unroll
        for (int kk = 0; kk < 16; kk++) {
            const float4 a  = *(const float4*)(&As[kk][ty << 2]);
            const float4 bq = *(const float4*)(&Bs[kk][tx << 2]);
            float ar[4] = {a.x, a.y, a.z, a.w};
            float br[4] = {bq.x, bq.y, bq.z, bq.w};
#pragma unroll
            for (int ii = 0; ii < 4; ii++)
#pragma unroll
                for (int jj = 0; jj < 4; jj++)
                    acc[ii][jj] = fmaf(ar[ii], br[jj], acc[ii][jj]);
        }
    }
#pragma unroll
    for (int ii = 0; ii < 4; ii++) {
        float4 o = make_float4(acc[ii][0], acc[ii][1], acc[ii][2], acc[ii][3]);
        *(float4*)(out + ((size_t)b*SEQ + mt + (ty<<2) + ii)*FDIM + nt + (tx<<2)) = o;
    }
}

// ---------------- launch ----------------------------------------------------
extern "C" void kernel_launch(void* const* d_in, const int* in_sizes, int n_in,
                              void* d_out, int out_size) {
    (void)in_sizes; (void)n_in; (void)out_size;
    const float* x  = (const float*)d_in[0];
    const float* qw = (const float*)d_in[1];
    const float* kw = (const float*)d_in[2];
    const float* vw = (const float*)d_in[3];
    float* out = (float*)d_out;

    cayley_kernel<<<1, 32>>>(qw, kw, vw);
    jacobi_logm_kernel<<<NMAT/8, 256>>>(x);
    transform_kernel<<<NMAT, dim3(32, 32)>>>();
    scores_kernel<<<dim3(SEQ/64, SEQ/64, BATCH), 256>>>();
    softmax_kernel<<<dim3(SEQ/128, BATCH), 128>>>();
    out_kernel<<<dim3(FDIM/64, SEQ/64, BATCH), 256>>>(out);
}

// round 2
// speedup vs baseline: 1.1280x; 1.1280x over previous
#include <cuda_runtime.h>
#include <math.h>

#define BATCH 16
#define SEQ   512
#define NDIM  32
#define NMAT  (BATCH*SEQ)     // 8192
#define FDIM  (NDIM*NDIM)     // 1024

// ---------------- scratch (static __device__, allocation-free) ----------------
__device__ float d_xl[NMAT*FDIM];          // logm result, diag zeroed
__device__ float d_q [NMAT*FDIM];
__device__ float d_k [NMAT*FDIM];
__device__ float d_v [NMAT*FDIM];
__device__ float d_sc[BATCH*SEQ*SEQ];      // exp(scores)
__device__ float d_isum[BATCH*SEQ];        // 1/colsum of exp
__device__ float d_C [3*FDIM];             // cayley matrices for q,k,v
__device__ float d_q2[NMAT];
__device__ float d_k2[NMAT];

// ---------------- Cayley: C = (I - X) (I + X)^-1, X = W - W^T -----------------
__global__ void cayley_kernel(const float* __restrict__ qw,
                              const float* __restrict__ kw,
                              const float* __restrict__ vw) {
    __shared__ float Aug[32][65];
    const int lane = threadIdx.x;
    for (int w = 0; w < 3; w++) {
        const float* W = (w == 0) ? qw : (w == 1) ? kw : vw;
        for (int r = 0; r < 32; r++) {
            float xv = W[r*32 + lane] - W[lane*32 + r];
            float id = (r == lane) ? 1.f : 0.f;
            Aug[r][lane]      = id - xv;   // A = I - X
            Aug[r][32 + lane] = id + xv;   // B = I + X
        }
        __syncwarp();
        for (int kp = 0; kp < 32; kp++) {
            float ip = 1.f / Aug[kp][kp];
            __syncwarp();
            Aug[kp][lane]      *= ip;
            Aug[kp][32 + lane] *= ip;
            __syncwarp();
            for (int r = 0; r < 32; r++) {
                if (r == kp) continue;
                float f = Aug[r][kp];
                Aug[r][lane]      = fmaf(-f, Aug[kp][lane],      Aug[r][lane]);
                Aug[r][32 + lane] = fmaf(-f, Aug[kp][32 + lane], Aug[r][32 + lane]);
            }
            __syncwarp();
        }
        for (int i = 0; i < 32; i++)
            d_C[w*FDIM + i*32 + lane] = Aug[lane][32 + i];
        __syncwarp();
    }
}

// ---------------- one-sided Jacobi logm: one warp per 32x32 SPD matrix --------
// Deferred scaling: column kept unscaled, scalar scale/iscale per column.
// Rotation update is then a single FMA per element.
__global__ void __launch_bounds__(256) jacobi_logm_kernel(const float* __restrict__ x) {
    const int lane = threadIdx.x & 31;
    const int wip  = threadIdx.x >> 5;
    const int m    = blockIdx.x * 8 + wip;
    const unsigned FULL = 0xffffffffu;
    const float* A = x + (size_t)m * FDIM;

    float g[32];
#pragma unroll
    for (int r = 0; r < 32; r++) g[r] = A[r*32 + lane];
    float nrm = 0.f;                 // true squared norm of this column
#pragma unroll
    for (int r = 0; r < 32; r++) nrm = fmaf(g[r], g[r], nrm);
    float scale = 1.f, iscale = 1.f;

    for (int sweep = 0; sweep < 10; sweep++) {
        bool any = false;
        for (int mm = 1; mm < 32; mm++) {
            const int partner = lane ^ mm;
            float h[32];
#pragma unroll
            for (int r = 0; r < 32; r++) h[r] = __shfl_xor_sync(FULL, g[r], mm);
            float dotv = 0.f;
#pragma unroll
            for (int r = 0; r < 32; r++) dotv = fmaf(g[r], h[r], dotv);
            float nrm_o = __shfl_xor_sync(FULL, nrm,   mm);
            float sc_o  = __shfl_xor_sync(FULL, scale, mm);
            float apq = dotv * scale * sc_o;     // true <g_p, g_q>
            const bool is_p = lane < partner;
            float app = is_p ? nrm : nrm_o;
            float aqq = is_p ? nrm_o : nrm;
            bool rot = apq * apq > 1e-10f * app * aqq;
            unsigned ball = __ballot_sync(FULL, rot);
            if (ball) {
                any = true;
                if (rot) {
                    float tau = (aqq - app) * 0.5f * (1.f / apq);
                    float t   = copysignf(1.f, tau) / (fabsf(tau) + sqrtf(fmaf(tau, tau, 1.f)));
                    float u   = fmaf(t, t, 1.f);
                    float c   = rsqrtf(u);       // cos
                    float rc  = sqrtf(u);        // 1/cos
                    float spt = is_p ? -t : t;
                    float coef = spt * sc_o * iscale;
#pragma unroll
                    for (int r = 0; r < 32; r++) g[r] = fmaf(coef, h[r], g[r]);
                    nrm = fmaf(spt, apq, nrm);   // app' = app - t*apq (true)
                    scale *= c; iscale *= rc;
                }
            }
        }
        // renormalize once per sweep to keep scale ~ 1
#pragma unroll
        for (int r = 0; r < 32; r++) g[r] *= scale;
        scale = 1.f; iscale = 1.f;
        if (!__any_sync(FULL, any)) break;
    }

    // exact norm; alpha = log(lambda)/lambda^2 = 0.5*log(nrm)/nrm
    float nx = 0.f;
#pragma unroll
    for (int r = 0; r < 32; r++) nx = fmaf(g[r], g[r], nx);
    float alpha = 0.5f * logf(nx) / nx;

    __shared__ float Gs[8][32][33];
    __shared__ float Al[8][32];
#pragma unroll
    for (int r = 0; r < 32; r++) Gs[wip][r][lane] = g[r];
    Al[wip][lane] = alpha;
    __syncwarp();

    float acc[32];
#pragma unroll
    for (int r = 0; r < 32; r++) acc[r] = 0.f;
#pragma unroll 4
    for (int t = 0; t < 32; t++) {
        float coef = Al[wip][t] * Gs[wip][lane][t];
#pragma unroll
        for (int r = 0; r < 32; r++)
            acc[r] = fmaf(coef, Gs[wip][r][t], acc[r]);
    }
    float* out = d_xl + (size_t)m * FDIM;
#pragma unroll
    for (int r = 0; r < 32; r++)
        out[r*32 + lane] = (r == lane) ? 0.f : acc[r];
}

// ---------------- transform: y_w = zero_diag(C_w xl C_w^T), + q2/k2 ----------
__global__ void transform_kernel() {
    const int m = blockIdx.x;
    const int j = threadIdx.x, i = threadIdx.y;
    __shared__ float Xs[32][33], Ts[32][33], Cs[32][33], red[32];
    Xs[i][j] = d_xl[(size_t)m*FDIM + i*32 + j];
    for (int w = 0; w < 3; w++) {
        __syncthreads();
        Cs[i][j] = d_C[w*FDIM + i*32 + j];
        __syncthreads();
        float t = 0.f;
#pragma unroll
        for (int kk = 0; kk < 32; kk++) t = fmaf(Cs[i][kk], Xs[kk][j], t);
        Ts[i][j] = t;
        __syncthreads();
        float y = 0.f;
#pragma unroll
        for (int kk = 0; kk < 32; kk++) y = fmaf(Ts[i][kk], Cs[j][kk], y);
        if (i == j) y = 0.f;
        float* o = (w == 0) ? d_q : (w == 1) ? d_k : d_v;
        o[(size_t)m*FDIM + i*32 + j] = y;
        if (w < 2) {
            float sq = y * y;
#pragma unroll
            for (int off = 16; off; off >>= 1) sq += __shfl_down_sync(0xffffffffu, sq, off);
            if (j == 0) red[i] = sq;
            __syncthreads();
            if (i == 0) {
                float v2 = red[j];
#pragma unroll
                for (int off = 16; off; off >>= 1) v2 += __shfl_down_sync(0xffffffffu, v2, off);
                if (j == 0) { if (w == 0) d_q2[m] = v2; else d_k2[m] = v2; }
            }
        }
    }
}

// ---------------- scores GEMM 128x128x16, 8x8 microtile, double-buffered -----
// S[j][i] = kf[j].qf[i]; writes exp(1/(1+log1p(sqrt(d2)))) directly.
__global__ void __launch_bounds__(256) scores_kernel() {
    const int b  = blockIdx.z;
    const int mt = blockIdx.y * 128;   // j rows (k side)
    const int nt = blockIdx.x * 128;   // i cols (q side)
    const float* Ab = d_k + (size_t)b * SEQ * FDIM;
    const float* Bb = d_q + (size_t)b * SEQ * FDIM;
    __shared__ __align__(16) float As[2][16][132];
    __shared__ __align__(16) float Bs[2][16][132];
    const int tid = threadIdx.x;
    const int lr = tid >> 2, lc = (tid & 3) << 2;
    const int tx = tid & 15, ty = tid >> 4;
    const int m0 = ty << 3, n0 = tx << 3;

    float acc[8][8];
#pragma unroll
    for (int ii = 0; ii < 8; ii++)
#pragma unroll
        for (int jj = 0; jj < 8; jj++) acc[ii][jj] = 0.f;

    const float* ap0 = Ab + (size_t)(mt + lr) * FDIM + lc;
    const float* ap1 = ap0 + (size_t)64 * FDIM;
    const float* bp0 = Bb + (size_t)(nt + lr) * FDIM + lc;
    const float* bp1 = bp0 + (size_t)64 * FDIM;

    {   // stage 0
        float4 a0 = *(const float4*)ap0, a1 = *(const float4*)ap1;
        float4 b0 = *(const float4*)bp0, b1 = *(const float4*)bp1;
        As[0][lc+0][lr]=a0.x; As[0][lc+1][lr]=a0.y; As[0][lc+2][lr]=a0.z; As[0][lc+3][lr]=a0.w;
        As[0][lc+0][lr+64]=a1.x; As[0][lc+1][lr+64]=a1.y; As[0][lc+2][lr+64]=a1.z; As[0][lc+3][lr+64]=a1.w;
        Bs[0][lc+0][lr]=b0.x; Bs[0][lc+1][lr]=b0.y; Bs[0][lc+2][lr]=b0.z; Bs[0][lc+3][lr]=b0.w;
        Bs[0][lc+0][lr+64]=b1.x; Bs[0][lc+1][lr+64]=b1.y; Bs[0][lc+2][lr+64]=b1.z; Bs[0][lc+3][lr+64]=b1.w;
    }
    __syncthreads();

    int buf = 0;
#pragma unroll 1
    for (int kt = 0; kt < FDIM; kt += 16) {
        float4 na0, na1, nb0, nb1;
        const bool more = (kt + 16 < FDIM);
        if (more) {
            na0 = *(const float4*)(ap0 + kt + 16);
            na1 = *(const float4*)(ap1 + kt + 16);
            nb0 = *(const float4*)(bp0 + kt + 16);
            nb1 = *(const float4*)(bp1 + kt + 16);
        }
#pragma unroll
        for (int kk = 0; kk < 16; kk++) {
            float a[8], bb[8];
            *(float4*)(a)     = *(const float4*)&As[buf][kk][m0];
            *(float4*)(a + 4) = *(const float4*)&As[buf][kk][m0 + 4];
            *(float4*)(bb)     = *(const float4*)&Bs[buf][kk][n0];
            *(float4*)(bb + 4) = *(const float4*)&Bs[buf][kk][n0 + 4];
#pragma unroll
            for (int ii = 0; ii < 8; ii++)
#pragma unroll
                for (int jj = 0; jj < 8; jj++)
                    acc[ii][jj] = fmaf(a[ii], bb[jj], acc[ii][jj]);
        }
        if (more) {
            const int nb = buf ^ 1;
            As[nb][lc+0][lr]=na0.x; As[nb][lc+1][lr]=na0.y; As[nb][lc+2][lr]=na0.z; As[nb][lc+3][lr]=na0.w;
            As[nb][lc+0][lr+64]=na1.x; As[nb][lc+1][lr+64]=na1.y; As[nb][lc+2][lr+64]=na1.z; As[nb][lc+3][lr+64]=na1.w;
            Bs[nb][lc+0][lr]=nb0.x; Bs[nb][lc+1][lr]=nb0.y; Bs[nb][lc+2][lr]=nb0.z; Bs[nb][lc+3][lr]=nb0.w;
            Bs[nb][lc+0][lr+64]=nb1.x; Bs[nb][lc+1][lr+64]=nb1.y; Bs[nb][lc+2][lr+64]=nb1.z; Bs[nb][lc+3][lr+64]=nb1.w;
        }
        __syncthreads();
        buf ^= 1;
    }

    float q2c[8];
#pragma unroll
    for (int jj = 0; jj < 8; jj++) q2c[jj] = d_q2[b*SEQ + nt + n0 + jj];
#pragma unroll
    for (int ii = 0; ii < 8; ii++) {
        float k2r = d_k2[b*SEQ + mt + m0 + ii];
        float o[8];
#pragma unroll
        for (int jj = 0; jj < 8; jj++) {
            float d2 = fmaxf(k2r + q2c[jj] - 2.f * acc[ii][jj], 1e-12f);
            float e  = sqrtf(d2);
            float sc = 1.f / (1.f + log1pf(e));
            o[jj] = __expf(sc);
        }
        float* dst = d_sc + ((size_t)b*SEQ + mt + m0 + ii)*SEQ + nt + n0;
        *(float4*)(dst)     = make_float4(o[0], o[1], o[2], o[3]);
        *(float4*)(dst + 4) = make_float4(o[4], o[5], o[6], o[7]);
    }
}

// ---------------- column-sum of exp scores ----------------------------------
__global__ void softsum_kernel() {
    const int b = blockIdx.y;
    const int i = blockIdx.x * 256 + threadIdx.x;
    const float* S = d_sc + (size_t)b * SEQ * SEQ;
    float sum = 0.f;
#pragma unroll 8
    for (int j = 0; j < SEQ; j++) sum += S[(size_t)j*SEQ + i];
    d_isum[b*SEQ + i] = 1.f / sum;
}

// ---------------- out GEMM 128x128x16: out[b,c,f] = sum_a e[c,a]*isum[a]*v[a,f]
__global__ void __launch_bounds__(256) out_kernel(float* __restrict__ out) {
    const int b  = blockIdx.z;
    const int mt = blockIdx.y * 128;   // c
    const int nt = blockIdx.x * 128;   // f
    const float* Ab = d_sc + (size_t)b * SEQ * SEQ;
    const float* Bb = d_v  + (size_t)b * SEQ * FDIM;
    const float* isum = d_isum + b * SEQ;
    __shared__ __align__(16) float As[2][16][132];
    __shared__ __align__(16) float Bs[2][16][132];
    const int tid = threadIdx.x;
    const int lr = tid >> 2, lc = (tid & 3) << 2;          // A loader
    const int br = tid >> 5, bc = (tid & 31) << 2;         // B loader: rows br, br+8
    const int tx = tid & 15, ty = tid >> 4;
    const int m0 = ty << 3, n0 = tx << 3;

    float acc[8][8];
#pragma unroll
    for (int ii = 0; ii < 8; ii++)
#pragma unroll
        for (int jj = 0; jj < 8; jj++) acc[ii][jj] = 0.f;

    const float* ap0 = Ab + (size_t)(mt + lr) * SEQ + lc;
    const float* ap1 = ap0 + (size_t)64 * SEQ;
    const float* bq0 = Bb + (size_t)br * FDIM + nt + bc;
    const float* bq1 = bq0 + (size_t)8 * FDIM;

    {
        float4 a0 = *(const float4*)ap0, a1 = *(const float4*)ap1;
        float4 v0 = *(const float4*)bq0, v1 = *(const float4*)bq1;
        float s0 = isum[br], s1 = isum[br + 8];
        As[0][lc+0][lr]=a0.x; As[0][lc+1][lr]=a0.y; As[0][lc+2][lr]=a0.z; As[0][lc+3][lr]=a0.w;
        As[0][lc+0][lr+64]=a1.x; As[0][lc+1][lr+64]=a1.y; As[0][lc+2][lr+64]=a1.z; As[0][lc+3][lr+64]=a1.w;
        *(float4*)&Bs[0][br][bc]     = make_float4(v0.x*s0, v0.y*s0, v0.z*s0, v0.w*s0);
        *(float4*)&Bs[0][br+8][bc]   = make_float4(v1.x*s1, v1.y*s1, v1.z*s1, v1.w*s1);
    }
    __syncthreads();

    int buf = 0;
#pragma unroll 1
    for (int kt = 0; kt < SEQ; kt += 16) {
        float4 na0, na1, nv0, nv1;
        float s0 = 0.f, s1 = 0.f;
        const bool more = (kt + 16 < SEQ);
        if (more) {
            na0 = *(const float4*)(ap0 + kt + 16);
            na1 = *(const float4*)(ap1 + kt + 16);
            nv0 = *(const float4*)(bq0 + (size_t)(kt + 16) * FDIM);
            nv1 = *(const float4*)(bq1 + (size_t)(kt + 16) * FDIM);
            s0 = isum[kt + 16 + br];
            s1 = isum[kt + 16 + br + 8];
        }
#pragma unroll
        for (int kk = 0; kk < 16; kk++) {
            float a[8], bb[8];
            *(float4*)(a)     = *(const float4*)&As[buf][kk][m0];
            *(float4*)(a + 4) = *(const float4*)&As[buf][kk][m0 + 4];
            *(float4*)(bb)     = *(const float4*)&Bs[buf][kk][n0];
            *(float4*)(bb + 4) = *(const float4*)&Bs[buf][kk][n0 + 4];
#pragma unroll
            for (int ii = 0; ii < 8; ii++)
#pragma unroll
                for (int jj = 0; jj < 8; jj++)
                    acc[ii][jj] = fmaf(a[ii], bb[jj], acc[ii][jj]);
        }
        if (more) {
            const int nb = buf ^ 1;
            As[nb][lc+0][lr]=na0.x; As[nb][lc+1][lr]=na0.y; As[nb][lc+2][lr]=na0.z; As[nb][lc+3][lr]=na0.w;
            As[nb][lc+0][lr+64]=na1.x; As[nb][lc+1][lr+64]=na1.y; As[nb][lc+2][lr+64]=na1.z; As[nb][lc+3][lr+64]=na1.w;
            *(float4*)&Bs[nb][br][bc]   = make_float4(nv0.x*s0, nv0.y*s0, nv0.z*s0, nv0.w*s0);
            *(float4*)&Bs[nb][br+8][bc] = make_float4(nv1.x*s1, nv1.y*s1, nv1.z*s1, nv1.w*s1);
        }
        __syncthreads();
        buf ^= 1;
    }

#pragma unroll
    for (int ii = 0; ii < 8; ii++) {
        float* dst = out + ((size_t)b*SEQ + mt + m0 + ii)*FDIM + nt + n0;
        *(float4*)(dst)     = make_float4(acc[ii][0], acc[ii][1], acc[ii][2], acc[ii][3]);
        *(float4*)(dst + 4) = make_float4(acc[ii][4], acc[ii][5], acc[ii][6], acc[ii][7]);
    }
}

// ---------------- launch ----------------------------------------------------
extern "C" void kernel_launch(void* const* d_in, const int* in_sizes, int n_in,
                              void* d_out, int out_size) {
    (void)in_sizes; (void)n_in; (void)out_size;
    const float* x  = (const float*)d_in[0];
    const float* qw = (const float*)d_in[1];
    const float* kw = (const float*)d_in[2];
    const float* vw = (const float*)d_in[3];
    float* out = (float*)d_out;

    cayley_kernel<<<1, 32>>>(qw, kw, vw);
    jacobi_logm_kernel<<<NMAT/8, 256>>>(x);
    transform_kernel<<<NMAT, dim3(32, 32)>>>();
    scores_kernel<<<dim3(SEQ/128, SEQ/128, BATCH), 256>>>();
    softsum_kernel<<<dim3(SEQ/256, BATCH), 256>>>();
    out_kernel<<<dim3(FDIM/128, SEQ/128, BATCH), 256>>>(out);
}